// round 2
// baseline (speedup 1.0000x reference)
#include <cuda_runtime.h>
#include <math.h>

// Problem constants (shapes fixed by the dataset)
#define BROWS 16384
#define DDIM  2048
#define EEXP  64
#define NCOL  128   // gate logits [0,64) | noise logits [64,128)

// GEMM tiling
#define BM 128
#define BN 128
#define BK 16
#define TM 8
#define TN 8
#define LDT 132           // padded smem stride: 132*4B = 528B, 16B-aligned
#define NTILES (DDIM / BK)

// Scratch for logits: 16384 * 128 * 4 = 8 MB (static __device__, allowed)
__device__ float g_logits[(size_t)BROWS * NCOL];

__global__ __launch_bounds__(256, 1)
void sg_gemm(const float* __restrict__ x,
             const float* __restrict__ gw,
             const float* __restrict__ nw)
{
    // double-buffered transposed tiles: [buf][k][m]
    __shared__ float As[2][BK][LDT];
    __shared__ float Bs[2][BK][LDT];

    const int tid = threadIdx.x;
    const int m0  = blockIdx.x * BM;
    const int tx  = tid & 15;   // 0..15 -> output col group
    const int ty  = tid >> 4;   // 0..15 -> output row group

    // Global load mapping: each thread loads 2 float4 from A and 2 from W per tile
    const int lrow = tid >> 2;        // 0..63
    const int lcol = (tid & 3) * 4;   // 0,4,8,12

    const float* aptr0 = x  + (size_t)(m0 + lrow)      * DDIM + lcol;
    const float* aptr1 = x  + (size_t)(m0 + lrow + 64) * DDIM + lcol;
    // combined weight matrix row j: j<64 -> gate[j], j>=64 -> noise[j-64]
    const float* wptr0 = gw + (size_t)lrow * DDIM + lcol;   // rows 0..63
    const float* wptr1 = nw + (size_t)lrow * DDIM + lcol;   // rows 64..127

    float acc[TM][TN];
#pragma unroll
    for (int i = 0; i < TM; ++i)
#pragma unroll
        for (int j = 0; j < TN; ++j) acc[i][j] = 0.f;

    // preload tile 0 into registers, stage into buffer 0
    float4 ra0 = *(const float4*)(aptr0);
    float4 ra1 = *(const float4*)(aptr1);
    float4 rw0 = *(const float4*)(wptr0);
    float4 rw1 = *(const float4*)(wptr1);

    As[0][lcol + 0][lrow]      = ra0.x;
    As[0][lcol + 1][lrow]      = ra0.y;
    As[0][lcol + 2][lrow]      = ra0.z;
    As[0][lcol + 3][lrow]      = ra0.w;
    As[0][lcol + 0][lrow + 64] = ra1.x;
    As[0][lcol + 1][lrow + 64] = ra1.y;
    As[0][lcol + 2][lrow + 64] = ra1.z;
    As[0][lcol + 3][lrow + 64] = ra1.w;
    Bs[0][lcol + 0][lrow]      = rw0.x;
    Bs[0][lcol + 1][lrow]      = rw0.y;
    Bs[0][lcol + 2][lrow]      = rw0.z;
    Bs[0][lcol + 3][lrow]      = rw0.w;
    Bs[0][lcol + 0][lrow + 64] = rw1.x;
    Bs[0][lcol + 1][lrow + 64] = rw1.y;
    Bs[0][lcol + 2][lrow + 64] = rw1.z;
    Bs[0][lcol + 3][lrow + 64] = rw1.w;
    __syncthreads();

    int cur = 0;
    for (int t = 0; t < NTILES; ++t) {
        // prefetch next tile into registers (overlaps FFMA below)
        const bool have_next = (t + 1 < NTILES);
        if (have_next) {
            const int off = (t + 1) * BK;
            ra0 = *(const float4*)(aptr0 + off);
            ra1 = *(const float4*)(aptr1 + off);
            rw0 = *(const float4*)(wptr0 + off);
            rw1 = *(const float4*)(wptr1 + off);
        }

        // mainloop over this K tile (reads buffer `cur`)
#pragma unroll
        for (int k = 0; k < BK; ++k) {
            float4 a0 = *(const float4*)&As[cur][k][ty * TM];
            float4 a1 = *(const float4*)&As[cur][k][ty * TM + 4];
            float4 b0 = *(const float4*)&Bs[cur][k][tx * TN];
            float4 b1 = *(const float4*)&Bs[cur][k][tx * TN + 4];
            float av[TM] = {a0.x, a0.y, a0.z, a0.w, a1.x, a1.y, a1.z, a1.w};
            float bv[TN] = {b0.x, b0.y, b0.z, b0.w, b1.x, b1.y, b1.z, b1.w};
#pragma unroll
            for (int i = 0; i < TM; ++i)
#pragma unroll
                for (int j = 0; j < TN; ++j)
                    acc[i][j] = fmaf(av[i], bv[j], acc[i][j]);
        }

        if (have_next) {
            const int nxt = cur ^ 1;   // stores target the idle buffer: no pre-store barrier
            As[nxt][lcol + 0][lrow]      = ra0.x;
            As[nxt][lcol + 1][lrow]      = ra0.y;
            As[nxt][lcol + 2][lrow]      = ra0.z;
            As[nxt][lcol + 3][lrow]      = ra0.w;
            As[nxt][lcol + 0][lrow + 64] = ra1.x;
            As[nxt][lcol + 1][lrow + 64] = ra1.y;
            As[nxt][lcol + 2][lrow + 64] = ra1.z;
            As[nxt][lcol + 3][lrow + 64] = ra1.w;
            Bs[nxt][lcol + 0][lrow]      = rw0.x;
            Bs[nxt][lcol + 1][lrow]      = rw0.y;
            Bs[nxt][lcol + 2][lrow]      = rw0.z;
            Bs[nxt][lcol + 3][lrow]      = rw0.w;
            Bs[nxt][lcol + 0][lrow + 64] = rw1.x;
            Bs[nxt][lcol + 1][lrow + 64] = rw1.y;
            Bs[nxt][lcol + 2][lrow + 64] = rw1.z;
            Bs[nxt][lcol + 3][lrow + 64] = rw1.w;
            __syncthreads();           // all compute on `cur` done + next buffer visible
            cur = nxt;
        }
    }

    // write logits tile
#pragma unroll
    for (int i = 0; i < TM; ++i) {
        const int row = m0 + ty * TM + i;
        float* dst = g_logits + (size_t)row * NCOL + tx * TN;
        *(float4*)(dst)     = make_float4(acc[i][0], acc[i][1], acc[i][2], acc[i][3]);
        *(float4*)(dst + 4) = make_float4(acc[i][4], acc[i][5], acc[i][6], acc[i][7]);
    }
}

__device__ __forceinline__ float softplus_stable(float z)
{
    // log(1+exp(z)) = max(z,0) + log1p(exp(-|z|))
    return fmaxf(z, 0.f) + log1pf(expf(-fabsf(z)));
}

__global__ __launch_bounds__(256, 4)
void sg_gate(const float* __restrict__ noise, float* __restrict__ out)
{
    const int b = blockIdx.x * blockDim.x + threadIdx.x;
    if (b >= BROWS) return;

    const float4* lg = (const float4*)(g_logits + (size_t)b * NCOL);
    const float4* nz = (const float4*)(noise    + (size_t)b * EEXP);

    float v1 = -INFINITY, v2 = -INFINITY;
    int   i1 = -1, i2 = -1;

#pragma unroll
    for (int g = 0; g < 16; ++g) {
        float4 c = lg[g];        // clean logits e = 4g..4g+3
        float4 s = lg[16 + g];   // noisy logits
        float4 n = nz[g];        // noise
        float ev[4];
        ev[0] = c.x + n.x * softplus_stable(s.x);
        ev[1] = c.y + n.y * softplus_stable(s.y);
        ev[2] = c.z + n.z * softplus_stable(s.z);
        ev[3] = c.w + n.w * softplus_stable(s.w);
#pragma unroll
        for (int c4 = 0; c4 < 4; ++c4) {
            const float v = ev[c4];
            const int   e = 4 * g + c4;
            if (v > v1)      { v2 = v1; i2 = i1; v1 = v; i1 = e; }
            else if (v > v2) { v2 = v;  i2 = e; }
        }
    }

    // softmax over the two selected (v1 >= v2)
    const float ex = expf(v2 - v1);     // <= 1
    const float p1 = 1.f / (1.f + ex);
    const float p2 = 1.f - p1;

    float* o = out + (size_t)b * EEXP;
#pragma unroll
    for (int g = 0; g < 16; ++g) {
        const int e = 4 * g;
        float4 v;
        v.x = (e     == i1) ? p1 : ((e     == i2) ? p2 : 0.f);
        v.y = (e + 1 == i1) ? p1 : ((e + 1 == i2) ? p2 : 0.f);
        v.z = (e + 2 == i1) ? p1 : ((e + 2 == i2) ? p2 : 0.f);
        v.w = (e + 3 == i1) ? p1 : ((e + 3 == i2) ? p2 : 0.f);
        *(float4*)(o + e) = v;
    }
}

extern "C" void kernel_launch(void* const* d_in, const int* in_sizes, int n_in,
                              void* d_out, int out_size)
{
    const float* x     = (const float*)d_in[0];
    const float* gw    = (const float*)d_in[1];
    const float* nw    = (const float*)d_in[2];
    const float* noise = (const float*)d_in[3];
    // d_in[4] is k (=2), compile-time constant here

    sg_gemm<<<BROWS / BM, 256>>>(x, gw, nw);
    sg_gate<<<BROWS / 256, 256>>>(noise, (float*)d_out);
}